// round 12
// baseline (speedup 1.0000x reference)
#include <cuda_runtime.h>
#include <math.h>

#define B      8192
#define H      512
#define V      128
#define STEPS  127
#define R      14      // rows per CTA
#define RH     7       // rows per thread-half
#define NT     512
#define GRID   ((B + R - 1) / R)   // 586

typedef unsigned long long ull;

// ---------------- device scratch (paired weight layouts) ----------------
// Whh_p[kk][k][g] = float2( W_hh[(g*512+k)*512+kk], W_hh[(g*512+k+256)*512+kk] ), kk pad +2
__device__ __align__(16) float2 g_Whh_p[(H + 2) * 256 * 4];
// Wih_p[tok][k][g] = float2( W_ih[(g*512+k)*128+tok], W_ih[(g*512+k+256)*128+tok] )
__device__ __align__(16) float2 g_Wih_p[V * 256 * 4];
// b_p[k][g] = float2( b[g*512+k], b[g*512+k+256] ),  b = b_ih + b_hh
__device__ __align__(16) float2 g_b_p[256 * 4];
// Wcz_p[kk][k] = float2( W_cz[k][kk], W_cz[k+256][kk] ), kk pad +2
__device__ __align__(16) float2 g_Wcz_p[(H + 2) * 256];
// Wfc_p[kk][vp] = float2( W_fc[vp][kk], W_fc[vp+64][kk] ), kk pad +2
__device__ __align__(16) float2 g_Wfc_p[(H + 2) * 64];

// ---------------- f32x2 helpers ----------------
__device__ __forceinline__ ull pack2(float lo, float hi) {
    ull r; asm("mov.b64 %0, {%1, %2};" : "=l"(r) : "f"(lo), "f"(hi)); return r;
}
__device__ __forceinline__ void unpack2(ull v, float& lo, float& hi) {
    asm("mov.b64 {%0, %1}, %2;" : "=f"(lo), "=f"(hi) : "l"(v));
}
__device__ __forceinline__ ull fma2(ull a, ull b, ull c) {
    ull d; asm("fma.rn.f32x2 %0, %1, %2, %3;" : "=l"(d) : "l"(a), "l"(b), "l"(c)); return d;
}
__device__ __forceinline__ ull add2(ull a, ull b) {
    ull d; asm("add.rn.f32x2 %0, %1, %2;" : "=l"(d) : "l"(a), "l"(b)); return d;
}
__device__ __forceinline__ float sigf(float x) { return 1.0f / (1.0f + expf(-x)); }

// ---------------- prep: build paired layouts ----------------
__global__ void prep_kernel(const float* __restrict__ W_ih, const float* __restrict__ W_hh,
                            const float* __restrict__ b_ih, const float* __restrict__ b_hh,
                            const float* __restrict__ W_cz, const float* __restrict__ W_fc)
{
    int i = blockIdx.x * blockDim.x + threadIdx.x;
    int stride = gridDim.x * blockDim.x;
    for (int idx = i; idx < H * 256 * 4; idx += stride) {
        int kk = idx >> 10, rem = idx & 1023;
        int k = rem >> 2, g = rem & 3;
        g_Whh_p[idx] = make_float2(W_hh[(g * H + k) * H + kk],
                                   W_hh[(g * H + k + 256) * H + kk]);
    }
    for (int idx = i; idx < V * 256 * 4; idx += stride) {
        int t = idx >> 10, rem = idx & 1023;
        int k = rem >> 2, g = rem & 3;
        g_Wih_p[idx] = make_float2(W_ih[(g * H + k) * V + t],
                                   W_ih[(g * H + k + 256) * V + t]);
    }
    for (int idx = i; idx < 256 * 4; idx += stride) {
        int k = idx >> 2, g = idx & 3;
        g_b_p[idx] = make_float2(b_ih[g * H + k] + b_hh[g * H + k],
                                 b_ih[g * H + k + 256] + b_hh[g * H + k + 256]);
    }
    for (int idx = i; idx < H * 256; idx += stride) {
        int kk = idx >> 8, k = idx & 255;
        g_Wcz_p[idx] = make_float2(W_cz[k * H + kk], W_cz[(k + 256) * H + kk]);
    }
    for (int idx = i; idx < H * 64; idx += stride) {
        int kk = idx >> 6, v = idx & 63;
        g_Wfc_p[idx] = make_float2(W_fc[v * H + kk], W_fc[(v + 64) * H + kk]);
    }
}

// ---------------- main persistent LSTM kernel ----------------
__global__ __launch_bounds__(NT, 1)
void lstm_main(const float* __restrict__ z, const float* __restrict__ b_cz,
               const float* __restrict__ b_fc, float* __restrict__ out)
{
    extern __shared__ char smem[];
    ull*   dupA     = (ull*)smem;              // R*H : (h,h) duplicated pairs
    ull*   dupB     = dupA + R * H;            // R*H
    ull*   shc      = dupB + R * H;            // R*256 : c packed (c_k, c_k+256)
    float* sh_logit = (float*)(shc + R * 256); // R*V
    int*   sh_tok   = (int*)(sh_logit + R * V);

    const int tid  = threadIdx.x;
    const int row0 = blockIdx.x * R;

    // ---- load z (= h0) duplicated into dupA ----
    for (int idx = tid; idx < R * H; idx += NT) {
        int r = idx >> 9, kk = idx & 511;
        int gr = row0 + r;
        float v = (gr < B) ? z[(size_t)gr * H + kk] : 0.f;
        dupA[idx] = pack2(v, v);
    }
    if (tid < R) sh_tok[tid] = 0;
    __syncthreads();

    const int k     = tid & 255;
    const int rh    = tid >> 8;        // 0 or 1
    const int rbase = rh * RH;

    // ---- c0 = relu(z @ W_cz^T + b_cz) -> shc (packed over k,k+256) ----
    {
        ull a[RH];
        ull b2 = pack2(b_cz[k], b_cz[k + 256]);
        #pragma unroll
        for (int p = 0; p < RH; ++p) a[p] = b2;
        const ull* wp = (const ull*)g_Wcz_p + k;     // stride 256 per kk
        const ull* hp = dupA + rbase * H;
        ull w0 = wp[0], w1 = wp[256];
        for (int kk = 0; kk < H; kk += 2) {
            ull n0 = wp[(size_t)(kk + 2) * 256];
            ull n1 = wp[(size_t)(kk + 3) * 256];
            #pragma unroll
            for (int p = 0; p < RH; ++p) a[p] = fma2(hp[p * H + kk], w0, a[p]);
            #pragma unroll
            for (int p = 0; p < RH; ++p) a[p] = fma2(hp[p * H + kk + 1], w1, a[p]);
            w0 = n0; w1 = n1;
        }
        #pragma unroll
        for (int p = 0; p < RH; ++p) {
            float x0, x1; unpack2(a[p], x0, x1);
            shc[(rbase + p) * 256 + k] = pack2(fmaxf(x0, 0.f), fmaxf(x1, 0.f));
        }
    }
    __syncthreads();

    // hoisted constants
    const ulonglong2* bbp = (const ulonglong2*)g_b_p + k * 2;
    const ulonglong2  bb01 = bbp[0], bb23 = bbp[1];   // gates (0,1), (2,3)
    const int vp  = tid & 63;
    const int grp = tid >> 6;                       // 0..7
    const int nr  = (grp < 6) ? 2 : 1;
    const int r0f = (grp < 6) ? grp * 2 : 12 + (grp - 6);
    const ull bf2 = pack2(b_fc[vp], b_fc[vp + 64]);

    const ulonglong2* Whh = (const ulonglong2*)g_Whh_p + k * 2;   // per kk: +512 ull2

    for (int step = 0; step < STEPS; ++step) {
        ull* hc = (step & 1) ? dupB : dupA;
        ull* hn = (step & 1) ? dupA : dupB;

        // ---- gates: thread owns k-pair (k, k+256), all 4 gates, 7 rows ----
        {
            ull a0[RH], a1[RH], a2[RH], a3[RH];
            #pragma unroll
            for (int p = 0; p < RH; ++p) {
                int t = sh_tok[rbase + p];
                const ulonglong2* wi = (const ulonglong2*)g_Wih_p + ((size_t)t * 256 + k) * 2;
                ulonglong2 w01 = wi[0], w23 = wi[1];
                a0[p] = add2(bb01.x, w01.x);
                a1[p] = add2(bb01.y, w01.y);
                a2[p] = add2(bb23.x, w23.x);
                a3[p] = add2(bb23.y, w23.y);
            }
            const ull* hp = hc + rbase * H;
            ulonglong2 wA0 = Whh[0],   wB0 = Whh[1];
            ulonglong2 wA1 = Whh[512], wB1 = Whh[513];
            for (int kk = 0; kk < H; kk += 2) {
                ulonglong2 nA0 = Whh[(size_t)(kk + 2) * 512];
                ulonglong2 nB0 = Whh[(size_t)(kk + 2) * 512 + 1];
                ulonglong2 nA1 = Whh[(size_t)(kk + 3) * 512];
                ulonglong2 nB1 = Whh[(size_t)(kk + 3) * 512 + 1];
                #pragma unroll
                for (int p = 0; p < RH; ++p) {
                    ull h2 = hp[p * H + kk];
                    a0[p] = fma2(h2, wA0.x, a0[p]);
                    a1[p] = fma2(h2, wA0.y, a1[p]);
                    a2[p] = fma2(h2, wB0.x, a2[p]);
                    a3[p] = fma2(h2, wB0.y, a3[p]);
                }
                #pragma unroll
                for (int p = 0; p < RH; ++p) {
                    ull h2 = hp[p * H + kk + 1];
                    a0[p] = fma2(h2, wA1.x, a0[p]);
                    a1[p] = fma2(h2, wA1.y, a1[p]);
                    a2[p] = fma2(h2, wB1.x, a2[p]);
                    a3[p] = fma2(h2, wB1.y, a3[p]);
                }
                wA0 = nA0; wB0 = nB0; wA1 = nA1; wB1 = nB1;
            }
            // epilogue: nonlinearity + c update + duplicated h store
            #pragma unroll
            for (int p = 0; p < RH; ++p) {
                float i0, i1, f0, f1, g0, g1, o0, o1, c0v, c1v;
                unpack2(a0[p], i0, i1);
                unpack2(a1[p], f0, f1);
                unpack2(a2[p], g0, g1);
                unpack2(a3[p], o0, o1);
                unpack2(shc[(rbase + p) * 256 + k], c0v, c1v);
                float cn0 = sigf(f0) * c0v + sigf(i0) * tanhf(g0);
                float cn1 = sigf(f1) * c1v + sigf(i1) * tanhf(g1);
                float h0v = sigf(o0) * tanhf(cn0);
                float h1v = sigf(o1) * tanhf(cn1);
                shc[(rbase + p) * 256 + k] = pack2(cn0, cn1);
                hn[(rbase + p) * H + k]       = pack2(h0v, h0v);
                hn[(rbase + p) * H + k + 256] = pack2(h1v, h1v);
            }
        }
        __syncthreads();

        // ---- fc: logits over v-pairs (vp, vp+64); rows split across 8 groups ----
        {
            ull fa0 = bf2, fa1 = bf2;
            const ull* wf = (const ull*)g_Wfc_p + vp;    // stride 64 per kk
            const ull* hr = hn + r0f * H;
            ull w0 = wf[0], w1 = wf[64];
            for (int kk = 0; kk < H; kk += 2) {
                ull n0 = wf[(size_t)(kk + 2) * 64];
                ull n1 = wf[(size_t)(kk + 3) * 64];
                fa0 = fma2(hr[kk], w0, fa0);
                if (nr == 2) fa1 = fma2(hr[H + kk], w0, fa1);
                fa0 = fma2(hr[kk + 1], w1, fa0);
                if (nr == 2) fa1 = fma2(hr[H + kk + 1], w1, fa1);
                w0 = n0; w1 = n1;
            }
            #pragma unroll
            for (int j = 0; j < 2; ++j) {
                if (j >= nr) break;
                ull fa = j ? fa1 : fa0;
                float l0, l1; unpack2(fa, l0, l1);
                l0 = fmaxf(l0, 0.f); l1 = fmaxf(l1, 0.f);
                int r = r0f + j;
                sh_logit[r * V + vp]      = l0;
                sh_logit[r * V + vp + 64] = l1;
                int gr = row0 + r;
                if (gr < B) {
                    out[((size_t)gr * STEPS + step) * V + vp]      = l0;
                    out[((size_t)gr * STEPS + step) * V + vp + 64] = l1;
                }
            }
        }
        __syncthreads();

        // ---- greedy argmax per row (lowest index wins ties) ----
        {
            const int wid = tid >> 5, lane = tid & 31;
            if (wid < R) {
                int r = wid;
                float best = -1.f; int bi = 0;
                #pragma unroll
                for (int q = 0; q < 4; ++q) {
                    int vv = lane + 32 * q;
                    float val = sh_logit[r * V + vv];
                    if (val > best) { best = val; bi = vv; }
                }
                #pragma unroll
                for (int off = 16; off; off >>= 1) {
                    float ov = __shfl_xor_sync(0xffffffffu, best, off);
                    int   oi = __shfl_xor_sync(0xffffffffu, bi, off);
                    if (ov > best || (ov == best && oi < bi)) { best = ov; bi = oi; }
                }
                if (lane == 0) sh_tok[r] = bi;
            }
        }
        __syncthreads();
    }
}

// ---------------- launch ----------------
extern "C" void kernel_launch(void* const* d_in, const int* in_sizes, int n_in,
                              void* d_out, int out_size)
{
    const float* z    = (const float*)d_in[0];
    const float* W_ih = (const float*)d_in[1];
    const float* W_hh = (const float*)d_in[2];
    const float* b_ih = (const float*)d_in[3];
    const float* b_hh = (const float*)d_in[4];
    const float* W_cz = (const float*)d_in[5];
    const float* b_cz = (const float*)d_in[6];
    const float* W_fc = (const float*)d_in[7];
    const float* b_fc = (const float*)d_in[8];
    float* out = (float*)d_out;

    prep_kernel<<<1024, 256>>>(W_ih, W_hh, b_ih, b_hh, W_cz, W_fc);

    const int smem_bytes = 2 * R * H * (int)sizeof(ull)    // dup h double buffer (112 KB)
                         + R * 256 * (int)sizeof(ull)       // c state (28 KB)
                         + R * V * (int)sizeof(float)       // logits (7 KB)
                         + R * (int)sizeof(int) + 64;       // tokens
    cudaFuncSetAttribute(lstm_main, cudaFuncAttributeMaxDynamicSharedMemorySize, smem_bytes);
    lstm_main<<<GRID, NT, smem_bytes>>>(z, b_cz, b_fc, out);
}

// round 15
// speedup vs baseline: 1.3138x; 1.3138x over previous
#include <cuda_runtime.h>
#include <math.h>

#define B      8192
#define H      512
#define V      128
#define STEPS  127
#define R      14      // rows per CTA (2 CTAs/SM)
#define RP     7       // row pairs per CTA
#define NT     256     // threads per CTA

typedef unsigned long long ull;

// ---------------- device scratch ----------------
// W4hh[kk][k][g] = W_hh[g*512+k][kk] ; +4096 floats pad (2 kk rows) for distance-2 prefetch
__device__ __align__(16) float g_W4hh[H * H * 4 + 4096];
// W4ih[tok][k][g] = W_ih[g*512+k][tok]
__device__ __align__(16) float g_W4ih[V * H * 4];
// WTcz[kk][k] = W_cz[k][kk] ; +2H pad
__device__ float g_WTcz[H * H + 2 * H];
// WTfc[kk][v] = W_fc[v][kk] ; +2V pad
__device__ float g_WTfc[H * V + 2 * V];
// b4[k][g] = b_ih[g*512+k] + b_hh[g*512+k]
__device__ __align__(16) float g_b4[H * 4];

// ---------------- f32x2 packed-math helpers ----------------
__device__ __forceinline__ ull pack2(float lo, float hi) {
    ull r; asm("mov.b64 %0, {%1, %2};" : "=l"(r) : "f"(lo), "f"(hi)); return r;
}
__device__ __forceinline__ void unpack2(ull v, float& lo, float& hi) {
    asm("mov.b64 {%0, %1}, %2;" : "=f"(lo), "=f"(hi) : "l"(v));
}
__device__ __forceinline__ ull fma2(ull a, ull b, ull c) {
    ull d; asm("fma.rn.f32x2 %0, %1, %2, %3;" : "=l"(d) : "l"(a), "l"(b), "l"(c)); return d;
}
__device__ __forceinline__ float sigf(float x) { return 1.0f / (1.0f + expf(-x)); }

// ---------------- prep: weight reshuffles ----------------
__global__ void prep_kernel(const float* __restrict__ W_ih, const float* __restrict__ W_hh,
                            const float* __restrict__ b_ih, const float* __restrict__ b_hh,
                            const float* __restrict__ W_cz, const float* __restrict__ W_fc)
{
    int i = blockIdx.x * blockDim.x + threadIdx.x;
    int stride = gridDim.x * blockDim.x;
    for (int idx = i; idx < H * H * 4; idx += stride) {
        int kk = idx >> 11, rem = idx & 2047;
        int k = rem >> 2, g = rem & 3;
        g_W4hh[idx] = W_hh[(g * H + k) * H + kk];
    }
    for (int idx = i; idx < V * H * 4; idx += stride) {
        int t = idx >> 11, rem = idx & 2047;
        int k = rem >> 2, g = rem & 3;
        g_W4ih[idx] = W_ih[(g * H + k) * V + t];
    }
    for (int idx = i; idx < H * H; idx += stride) {
        int kk = idx >> 9, k = idx & 511;
        g_WTcz[idx] = W_cz[k * H + kk];
    }
    for (int idx = i; idx < H * V; idx += stride) {
        int kk = idx >> 7, v = idx & 127;
        g_WTfc[idx] = W_fc[v * H + kk];
    }
    for (int idx = i; idx < H * 4; idx += stride) {
        int k = idx >> 2, g = idx & 3;
        g_b4[idx] = b_ih[g * H + k] + b_hh[g * H + k];
    }
}

// ---------------- main persistent LSTM kernel (2 CTAs/SM) ----------------
__global__ __launch_bounds__(NT, 2)
void lstm_main(const float* __restrict__ z, const float* __restrict__ b_cz,
               const float* __restrict__ b_fc, float* __restrict__ out)
{
    extern __shared__ char smem[];
    float2* shA      = (float2*)smem;                 // RP*H  (h row-pair buffer, even steps in)
    float2* shB      = shA + RP * H;                  // RP*H
    float*  sh_logit = (float*)(shB + RP * H);        // R*V
    int*    sh_tok   = (int*)(sh_logit + R * V);      // R

    const int tid  = threadIdx.x;
    const int row0 = blockIdx.x * R;
    if (row0 >= B) return;

    // ---- load z (= h0) into shA, packed as row pairs ----
    for (int idx = tid; idx < RP * H; idx += NT) {
        int rp = idx / H, kk = idx - rp * H;
        int r0 = row0 + 2 * rp;
        float a = (r0     < B) ? z[(size_t)r0 * H + kk]       : 0.f;
        float b = (r0 + 1 < B) ? z[(size_t)(r0 + 1) * H + kk] : 0.f;
        shA[rp * H + kk] = make_float2(a, b);
    }
    if (tid < R) sh_tok[tid] = 0;
    __syncthreads();

    // ---- c0 = relu(z @ W_cz^T + b_cz), kept in registers ----
    ull c2[2][RP];
    #pragma unroll
    for (int kp = 0; kp < 2; ++kp) {
        const int k = tid + kp * NT;
        ull a[RP];
        float bz = b_cz[k];
        #pragma unroll
        for (int rp = 0; rp < RP; ++rp) a[rp] = pack2(bz, bz);
        const float* wp = g_WTcz + k;
        const ull* hp = (const ull*)shA;
        float w0 = wp[0], w1 = wp[H];
        for (int kk = 0; kk < H; kk += 2) {
            float n0 = wp[(size_t)(kk + 2) * H];
            float n1 = wp[(size_t)(kk + 3) * H];
            ull wd0 = pack2(w0, w0), wd1 = pack2(w1, w1);
            #pragma unroll
            for (int rp = 0; rp < RP; ++rp) {
                ulonglong2 h2 = *(const ulonglong2*)&hp[rp * H + kk];   // LDS.128
                a[rp] = fma2(h2.x, wd0, a[rp]);
                a[rp] = fma2(h2.y, wd1, a[rp]);
            }
            w0 = n0; w1 = n1;
        }
        #pragma unroll
        for (int rp = 0; rp < RP; ++rp) {
            float x0, x1; unpack2(a[rp], x0, x1);
            c2[kp][rp] = pack2(fmaxf(x0, 0.f), fmaxf(x1, 0.f));
        }
    }

    const float4* W4hh = (const float4*)g_W4hh;
    const float4* W4ih = (const float4*)g_W4ih;
    const float4* b4p  = (const float4*)g_b4;

    for (int step = 0; step < STEPS; ++step) {
        float2* hc = (step & 1) ? shB : shA;
        float2* hn = (step & 1) ? shA : shB;
        const ull* hp = (const ull*)hc;
        ull* ho = (ull*)hn;

        // ---- gates + state update ----
        #pragma unroll
        for (int kp = 0; kp < 2; ++kp) {
            const int k = tid + kp * NT;
            float4 bb = b4p[k];
            ull a0[RP], a1[RP], a2[RP], a3[RP];
            #pragma unroll
            for (int rp = 0; rp < RP; ++rp) {
                float4 wi0 = W4ih[sh_tok[2 * rp] * H + k];
                float4 wi1 = W4ih[sh_tok[2 * rp + 1] * H + k];
                a0[rp] = pack2(bb.x + wi0.x, bb.x + wi1.x);
                a1[rp] = pack2(bb.y + wi0.y, bb.y + wi1.y);
                a2[rp] = pack2(bb.z + wi0.z, bb.z + wi1.z);
                a3[rp] = pack2(bb.w + wi0.w, bb.w + wi1.w);
            }
            const float4* wp = W4hh + k;
            float4 w0 = wp[0], w1 = wp[H];
            for (int kk = 0; kk < H; kk += 2) {
                float4 n0 = wp[(size_t)(kk + 2) * H];
                float4 n1 = wp[(size_t)(kk + 3) * H];
                ull wx0 = pack2(w0.x, w0.x), wy0 = pack2(w0.y, w0.y);
                ull wz0 = pack2(w0.z, w0.z), ww0 = pack2(w0.w, w0.w);
                ull wx1 = pack2(w1.x, w1.x), wy1 = pack2(w1.y, w1.y);
                ull wz1 = pack2(w1.z, w1.z), ww1 = pack2(w1.w, w1.w);
                #pragma unroll
                for (int rp = 0; rp < RP; ++rp) {
                    ulonglong2 h2 = *(const ulonglong2*)&hp[rp * H + kk];   // LDS.128
                    a0[rp] = fma2(h2.x, wx0, a0[rp]);
                    a1[rp] = fma2(h2.x, wy0, a1[rp]);
                    a2[rp] = fma2(h2.x, wz0, a2[rp]);
                    a3[rp] = fma2(h2.x, ww0, a3[rp]);
                    a0[rp] = fma2(h2.y, wx1, a0[rp]);
                    a1[rp] = fma2(h2.y, wy1, a1[rp]);
                    a2[rp] = fma2(h2.y, wz1, a2[rp]);
                    a3[rp] = fma2(h2.y, ww1, a3[rp]);
                }
                w0 = n0; w1 = n1;
            }
            #pragma unroll
            for (int rp = 0; rp < RP; ++rp) {
                float i0, i1, f0, f1, g0, g1, o0, o1, cc0, cc1;
                unpack2(a0[rp], i0, i1);
                unpack2(a1[rp], f0, f1);
                unpack2(a2[rp], g0, g1);
                unpack2(a3[rp], o0, o1);
                unpack2(c2[kp][rp], cc0, cc1);
                float cn0 = sigf(f0) * cc0 + sigf(i0) * tanhf(g0);
                float cn1 = sigf(f1) * cc1 + sigf(i1) * tanhf(g1);
                float h0v = sigf(o0) * tanhf(cn0);
                float h1v = sigf(o1) * tanhf(cn1);
                c2[kp][rp] = pack2(cn0, cn1);
                ho[rp * H + k] = pack2(h0v, h1v);
            }
        }
        __syncthreads();

        // ---- fc: logits = relu(h_new @ W_fc^T + b_fc) ----
        {
            const int v  = tid & (V - 1);
            const int rh = tid >> 7;          // 0 or 1: row-half
            const int p0 = rh * 4;            // rh0: pairs 0..3, rh1: pairs 4..6
            ull fa[4];
            float bv = b_fc[v];
            #pragma unroll
            for (int p = 0; p < 4; ++p) fa[p] = pack2(bv, bv);
            const float* wf = g_WTfc + v;
            const ull* hpn = (const ull*)hn + (size_t)p0 * H;
            float w0 = wf[0], w1 = wf[V];
            for (int kk = 0; kk < H; kk += 2) {
                float n0 = wf[(size_t)(kk + 2) * V];
                float n1 = wf[(size_t)(kk + 3) * V];
                ull wd0 = pack2(w0, w0), wd1 = pack2(w1, w1);
                #pragma unroll
                for (int p = 0; p < 4; ++p)
                    if (p0 + p < RP) {
                        ulonglong2 h2 = *(const ulonglong2*)&hpn[p * H + kk];   // LDS.128
                        fa[p] = fma2(h2.x, wd0, fa[p]);
                        fa[p] = fma2(h2.y, wd1, fa[p]);
                    }
                w0 = n0; w1 = n1;
            }
            #pragma unroll
            for (int p = 0; p < 4; ++p) {
                if (p0 + p >= RP) break;
                float l0, l1; unpack2(fa[p], l0, l1);
                l0 = fmaxf(l0, 0.f); l1 = fmaxf(l1, 0.f);
                int r0 = (p0 + p) * 2;
                sh_logit[r0 * V + v]       = l0;
                sh_logit[(r0 + 1) * V + v] = l1;
                int gr0 = row0 + r0;
                if (gr0     < B) out[((size_t)gr0 * STEPS + step) * V + v]       = l0;
                if (gr0 + 1 < B) out[((size_t)(gr0 + 1) * STEPS + step) * V + v] = l1;
            }
        }
        __syncthreads();

        // ---- greedy argmax per row (lowest index wins ties) ----
        {
            const int wid = tid >> 5, lane = tid & 31;
            for (int r = wid; r < R; r += 8) {
                float best = -1.f; int bi = 0;
                #pragma unroll
                for (int q = 0; q < 4; ++q) {
                    int vv = lane + 32 * q;
                    float val = sh_logit[r * V + vv];
                    if (val > best) { best = val; bi = vv; }
                }
                #pragma unroll
                for (int off = 16; off; off >>= 1) {
                    float ov = __shfl_xor_sync(0xffffffffu, best, off);
                    int   oi = __shfl_xor_sync(0xffffffffu, bi, off);
                    if (ov > best || (ov == best && oi < bi)) { best = ov; bi = oi; }
                }
                if (lane == 0) sh_tok[r] = bi;
            }
        }
        __syncthreads();
    }
}

// ---------------- launch ----------------
extern "C" void kernel_launch(void* const* d_in, const int* in_sizes, int n_in,
                              void* d_out, int out_size)
{
    const float* z    = (const float*)d_in[0];
    const float* W_ih = (const float*)d_in[1];
    const float* W_hh = (const float*)d_in[2];
    const float* b_ih = (const float*)d_in[3];
    const float* b_hh = (const float*)d_in[4];
    const float* W_cz = (const float*)d_in[5];
    const float* b_cz = (const float*)d_in[6];
    const float* W_fc = (const float*)d_in[7];
    const float* b_fc = (const float*)d_in[8];
    float* out = (float*)d_out;

    prep_kernel<<<1024, 256>>>(W_ih, W_hh, b_ih, b_hh, W_cz, W_fc);

    const int smem_bytes = 2 * RP * H * (int)sizeof(float2)    // h double buffer (56 KB)
                         + R * V * (int)sizeof(float)          // logits (7 KB)
                         + R * (int)sizeof(int);               // tokens
    cudaFuncSetAttribute(lstm_main, cudaFuncAttributeMaxDynamicSharedMemorySize, smem_bytes);
    lstm_main<<<(B + R - 1) / R, NT, smem_bytes>>>(z, b_cz, b_fc, out);
}